// round 14
// baseline (speedup 1.0000x reference)
#include <cuda_runtime.h>
#include <cuda_bf16.h>
#include <cstdint>

#define CC 512
#define TT 8192
#define SEG_T 128
#define SEGS 64                  // TT / SEG_T
#define NCTA 1024                // 16 batch * 64 segs
#define NTHREADS 512
#define DIVC 512.0f
#define EPSV 1e-8f
#define FULL 0xffffffffu

// one 16B record per segment: {s, q, flag, pad}; flag 0=empty, 1=aggregate, 2=prefix
__device__ float4 g_rec[NCTA];

__global__ void init_rec_kernel() {
    int i = blockIdx.x * blockDim.x + threadIdx.x;
    if (i < NCTA) g_rec[i] = make_float4(0.f, 0.f, 0.f, 0.f);
}

__device__ __forceinline__ float4 ld_rec_vol(const float4* p) {
    float4 r;
    asm volatile("ld.volatile.global.v4.f32 {%0,%1,%2,%3}, [%4];"
                 : "=f"(r.x), "=f"(r.y), "=f"(r.z), "=f"(r.w) : "l"(p));
    return r;
}
__device__ __forceinline__ void st_rec_vol(float4* p, float s, float q, int flag) {
    asm volatile("st.volatile.global.v4.f32 [%0], {%1,%2,%3,%4};"
                 :: "l"(p), "f"(s), "f"(q), "f"(__int_as_float(flag)), "f"(0.f)
                 : "memory");
}

__global__ void __launch_bounds__(NTHREADS, 2)
newNormal_kernel(const float* __restrict__ x,
                 const float* __restrict__ gains,
                 const float* __restrict__ bias,
                 float* __restrict__ out) {
    __shared__ float4 ps[16][32];        // [warp][chunk] channel-sum partials  8 KB
    __shared__ float4 pq[16][32];        //                                     8 KB
    __shared__ float4 mean4[32], inv4[32];

    const int bid  = blockIdx.x;
    const int b    = bid >> 6;           // batch
    const int seg  = bid & 63;           // segment within row (ascending bid)
    const int t0   = seg * SEG_T;
    const int tid  = threadIdx.x;
    const int lane = tid & 31;           // chunk: fixed 4-t group (128 t total)
    const int w    = tid >> 5;           // 16 warps = 16 channel phases

    const float* xb = x + ((size_t)b * CC) * TT + t0 + 4 * lane;

    // ======== Pass 1: streaming read; warp instruction = 512B contiguous per row ========
    float4 s4 = make_float4(0.f, 0.f, 0.f, 0.f);
    float4 q4 = make_float4(0.f, 0.f, 0.f, 0.f);
#pragma unroll
    for (int iblk = 0; iblk < 4; iblk++) {
        float4 v[8];
#pragma unroll
        for (int u = 0; u < 8; u++) {
            const int c = (iblk * 8 + u) * 16 + w;        // channel
            v[u] = __ldg((const float4*)(xb + (size_t)c * TT));
        }
#pragma unroll
        for (int u = 0; u < 8; u++) {
            float4 t = v[u];
            s4.x += t.x; s4.y += t.y; s4.z += t.z; s4.w += t.w;
            q4.x = fmaf(t.x, t.x, q4.x); q4.y = fmaf(t.y, t.y, q4.y);
            q4.z = fmaf(t.z, t.z, q4.z); q4.w = fmaf(t.w, t.w, q4.w);
        }
    }
    ps[w][lane] = s4;
    pq[w][lane] = q4;
    __syncthreads();

    // ======== warp 0: final reduce + scan 128 + shallow look-back ========
    if (tid < 32) {
        float4 sv = make_float4(0.f,0.f,0.f,0.f), qv = make_float4(0.f,0.f,0.f,0.f);
#pragma unroll
        for (int w2 = 0; w2 < 16; w2++) {
            float4 a = ps[w2][lane];
            sv.x += a.x; sv.y += a.y; sv.z += a.z; sv.w += a.w;
            float4 c = pq[w2][lane];
            qv.x += c.x; qv.y += c.y; qv.z += c.z; qv.w += c.w;
        }
        // inclusive scan within the 4-t chunk
        float4 is, iq;
        is.x = sv.x; is.y = is.x + sv.y; is.z = is.y + sv.z; is.w = is.z + sv.w;
        iq.x = qv.x; iq.y = iq.x + qv.y; iq.z = iq.y + qv.z; iq.w = iq.z + qv.w;
        // scan chunk totals across all 32 lanes
        const float gs = is.w, gq = iq.w;
        float ssc = gs, qsc = gq;
#pragma unroll
        for (int d = 1; d < 32; d <<= 1) {
            float a = __shfl_up_sync(FULL, ssc, d);
            float c = __shfl_up_sync(FULL, qsc, d);
            if (lane >= d) { ssc += a; qsc += c; }
        }
        const float exg_s = ssc - gs, exg_q = qsc - gq;
        const float tot_s = __shfl_sync(FULL, ssc, 31);
        const float tot_q = __shfl_sync(FULL, qsc, 31);

        // decoupled look-back, depth <= 63 (warp-parallel, 32 records/round)
        float ex_s = 0.f, ex_q = 0.f;
        if (seg == 0) {
            if (lane == 0) st_rec_vol(&g_rec[bid], tot_s, tot_q, 2);
        } else {
            if (lane == 0) st_rec_vol(&g_rec[bid], tot_s, tot_q, 1);
            const int base = bid - seg;
            int p_hi = bid - 1;
            for (;;) {
                const int p = p_hi - lane;
                float rs, rq; int f;
                if (p >= base) {
                    float4 rr2 = ld_rec_vol(&g_rec[p]);
                    rs = rr2.x; rq = rr2.y; f = __float_as_int(rr2.z);
                } else { rs = 0.f; rq = 0.f; f = 2; }
                if (__ballot_sync(FULL, f == 0)) { __nanosleep(32); continue; }
                const unsigned m2 = __ballot_sync(FULL, f == 2);
                float cs, cq;
                if (m2) {
                    const int l2 = __ffs(m2) - 1;
                    cs = (lane <= l2) ? rs : 0.f;
                    cq = (lane <= l2) ? rq : 0.f;
                } else { cs = rs; cq = rq; }
#pragma unroll
                for (int d = 16; d; d >>= 1) {
                    cs += __shfl_down_sync(FULL, cs, d);
                    cq += __shfl_down_sync(FULL, cq, d);
                }
                ex_s += __shfl_sync(FULL, cs, 0);
                ex_q += __shfl_sync(FULL, cq, 0);
                if (m2) break;
                p_hi -= 32;
            }
            if (lane == 0) st_rec_vol(&g_rec[bid], ex_s + tot_s, ex_q + tot_q, 2);
        }

        // mean / rsqrt per t chunk
        {
            const float bs = ex_s + exg_s;
            const float bq = ex_q + exg_q;
            const int tb = t0 + 4 * lane;
            float4 m4, i4;
            {
                float dv = 1.0f / ((float)(tb + 1) * DIVC);
                float m = (bs + is.x) * dv;
                float var = fmaf(-m, m, (bq + iq.x) * dv);
                m4.x = m; i4.x = rsqrtf(var + EPSV);
            }
            {
                float dv = 1.0f / ((float)(tb + 2) * DIVC);
                float m = (bs + is.y) * dv;
                float var = fmaf(-m, m, (bq + iq.y) * dv);
                m4.y = m; i4.y = rsqrtf(var + EPSV);
            }
            {
                float dv = 1.0f / ((float)(tb + 3) * DIVC);
                float m = (bs + is.z) * dv;
                float var = fmaf(-m, m, (bq + iq.z) * dv);
                m4.z = m; i4.z = rsqrtf(var + EPSV);
            }
            {
                float dv = 1.0f / ((float)(tb + 4) * DIVC);
                float m = (bs + is.w) * dv;
                float var = fmaf(-m, m, (bq + iq.w) * dv);
                m4.w = m; i4.w = rsqrtf(var + EPSV);
            }
            mean4[lane] = m4;
            inv4[lane]  = i4;
        }
    }
    __syncthreads();

    // ======== Pass 2: re-read own 256KB (L2-hot), normalize, write ========
    {
        const float4 m4 = mean4[lane];
        const float4 i4 = inv4[lane];
        float* ob = out + ((size_t)b * CC) * TT + t0 + 4 * lane;
#pragma unroll
        for (int iblk = 0; iblk < 4; iblk++) {
            float4 v[8];
            float gg[8], bb[8];
#pragma unroll
            for (int u = 0; u < 8; u++) {
                const int c = (iblk * 8 + u) * 16 + w;
                v[u]  = __ldg((const float4*)(xb + (size_t)c * TT));
                gg[u] = __ldg(gains + c);
                bb[u] = __ldg(bias  + c);
            }
#pragma unroll
            for (int u = 0; u < 8; u++) {
                const int c = (iblk * 8 + u) * 16 + w;
                float4 t = v[u];
                float4 o;
                o.x = fmaf((t.x - m4.x) * i4.x, gg[u], bb[u]);
                o.y = fmaf((t.y - m4.y) * i4.y, gg[u], bb[u]);
                o.z = fmaf((t.z - m4.z) * i4.z, gg[u], bb[u]);
                o.w = fmaf((t.w - m4.w) * i4.w, gg[u], bb[u]);
                __stcs((float4*)(ob + (size_t)c * TT), o);
            }
        }
    }
}

extern "C" void kernel_launch(void* const* d_in, const int* in_sizes, int n_in,
                              void* d_out, int out_size) {
    (void)in_sizes; (void)n_in; (void)out_size;
    const float* x     = (const float*)d_in[0];
    const float* gains = (const float*)d_in[1];
    const float* bias  = (const float*)d_in[2];
    float* out = (float*)d_out;

    init_rec_kernel<<<NCTA / 256, 256>>>();
    newNormal_kernel<<<NCTA, NTHREADS>>>(x, gains, bias, out);
}

// round 15
// speedup vs baseline: 1.0721x; 1.0721x over previous
#include <cuda_runtime.h>
#include <cuda_bf16.h>
#include <cstdint>

#define CC 512
#define TT 8192
#define SEG_T 128
#define SEGS 64                  // TT / SEG_T
#define NCTA 1024                // 16 batch * 64 segs
#define NTHREADS 1024
#define DIVC 512.0f
#define EPSV 1e-8f
#define FULL 0xffffffffu

// one 16B record per segment: {s, q, flag, pad}; flag 0=empty, 1=aggregate, 2=prefix
__device__ float4 g_rec[NCTA];

__global__ void init_rec_kernel() {
    int i = blockIdx.x * blockDim.x + threadIdx.x;
    if (i < NCTA) g_rec[i] = make_float4(0.f, 0.f, 0.f, 0.f);
}

__device__ __forceinline__ float4 ld_rec_vol(const float4* p) {
    float4 r;
    asm volatile("ld.volatile.global.v4.f32 {%0,%1,%2,%3}, [%4];"
                 : "=f"(r.x), "=f"(r.y), "=f"(r.z), "=f"(r.w) : "l"(p));
    return r;
}
__device__ __forceinline__ void st_rec_vol(float4* p, float s, float q, int flag) {
    asm volatile("st.volatile.global.v4.f32 [%0], {%1,%2,%3,%4};"
                 :: "l"(p), "f"(s), "f"(q), "f"(__int_as_float(flag)), "f"(0.f)
                 : "memory");
}

__global__ void __launch_bounds__(NTHREADS, 1)
newNormal_kernel(const float* __restrict__ x,
                 const float* __restrict__ gains,
                 const float* __restrict__ bias,
                 float* __restrict__ out) {
    __shared__ float4 ps[32][32];        // [warp][chunk] channel-sum partials 16 KB
    __shared__ float4 pq[32][32];        //                                    16 KB
    __shared__ float4 mean4[32], inv4[32];

    const int bid  = blockIdx.x;
    const int b    = bid >> 6;           // batch
    const int seg  = bid & 63;           // segment within row (ascending bid)
    const int t0   = seg * SEG_T;
    const int tid  = threadIdx.x;
    const int lane = tid & 31;           // chunk: fixed 4-t group (128 t total)
    const int w    = tid >> 5;           // 32 warps = 32 channel phases

    const float* xb = x + ((size_t)b * CC) * TT + t0 + 4 * lane;

    // ======== Pass 1: streaming read; warp instruction = 512B contiguous per row ========
    float4 s4 = make_float4(0.f, 0.f, 0.f, 0.f);
    float4 q4 = make_float4(0.f, 0.f, 0.f, 0.f);
#pragma unroll
    for (int iblk = 0; iblk < 2; iblk++) {
        float4 v[8];
#pragma unroll
        for (int u = 0; u < 8; u++) {
            const int c = (iblk * 8 + u) * 32 + w;        // channel
            v[u] = __ldg((const float4*)(xb + (size_t)c * TT));
        }
#pragma unroll
        for (int u = 0; u < 8; u++) {
            float4 t = v[u];
            s4.x += t.x; s4.y += t.y; s4.z += t.z; s4.w += t.w;
            q4.x = fmaf(t.x, t.x, q4.x); q4.y = fmaf(t.y, t.y, q4.y);
            q4.z = fmaf(t.z, t.z, q4.z); q4.w = fmaf(t.w, t.w, q4.w);
        }
    }
    ps[w][lane] = s4;
    pq[w][lane] = q4;
    __syncthreads();

    // ======== warp 0: final reduce + scan 128 + shallow look-back ========
    if (tid < 32) {
        float4 sv = make_float4(0.f,0.f,0.f,0.f), qv = make_float4(0.f,0.f,0.f,0.f);
#pragma unroll
        for (int w2 = 0; w2 < 32; w2++) {
            float4 a = ps[w2][lane];
            sv.x += a.x; sv.y += a.y; sv.z += a.z; sv.w += a.w;
            float4 c = pq[w2][lane];
            qv.x += c.x; qv.y += c.y; qv.z += c.z; qv.w += c.w;
        }
        // inclusive scan within the 4-t chunk
        float4 is, iq;
        is.x = sv.x; is.y = is.x + sv.y; is.z = is.y + sv.z; is.w = is.z + sv.w;
        iq.x = qv.x; iq.y = iq.x + qv.y; iq.z = iq.y + qv.z; iq.w = iq.z + qv.w;
        // scan chunk totals across all 32 lanes
        const float gs = is.w, gq = iq.w;
        float ssc = gs, qsc = gq;
#pragma unroll
        for (int d = 1; d < 32; d <<= 1) {
            float a = __shfl_up_sync(FULL, ssc, d);
            float c = __shfl_up_sync(FULL, qsc, d);
            if (lane >= d) { ssc += a; qsc += c; }
        }
        const float exg_s = ssc - gs, exg_q = qsc - gq;
        const float tot_s = __shfl_sync(FULL, ssc, 31);
        const float tot_q = __shfl_sync(FULL, qsc, 31);

        // decoupled look-back, depth <= 63 (warp-parallel, 32 records/round)
        float ex_s = 0.f, ex_q = 0.f;
        if (seg == 0) {
            if (lane == 0) st_rec_vol(&g_rec[bid], tot_s, tot_q, 2);
        } else {
            if (lane == 0) st_rec_vol(&g_rec[bid], tot_s, tot_q, 1);
            const int base = bid - seg;
            int p_hi = bid - 1;
            for (;;) {
                const int p = p_hi - lane;
                float rs, rq; int f;
                if (p >= base) {
                    float4 rr2 = ld_rec_vol(&g_rec[p]);
                    rs = rr2.x; rq = rr2.y; f = __float_as_int(rr2.z);
                } else { rs = 0.f; rq = 0.f; f = 2; }
                if (__ballot_sync(FULL, f == 0)) { __nanosleep(32); continue; }
                const unsigned m2 = __ballot_sync(FULL, f == 2);
                float cs, cq;
                if (m2) {
                    const int l2 = __ffs(m2) - 1;
                    cs = (lane <= l2) ? rs : 0.f;
                    cq = (lane <= l2) ? rq : 0.f;
                } else { cs = rs; cq = rq; }
#pragma unroll
                for (int d = 16; d; d >>= 1) {
                    cs += __shfl_down_sync(FULL, cs, d);
                    cq += __shfl_down_sync(FULL, cq, d);
                }
                ex_s += __shfl_sync(FULL, cs, 0);
                ex_q += __shfl_sync(FULL, cq, 0);
                if (m2) break;
                p_hi -= 32;
            }
            if (lane == 0) st_rec_vol(&g_rec[bid], ex_s + tot_s, ex_q + tot_q, 2);
        }

        // mean / rsqrt per t chunk
        {
            const float bs = ex_s + exg_s;
            const float bq = ex_q + exg_q;
            const int tb = t0 + 4 * lane;
            float4 m4, i4;
            {
                float dv = 1.0f / ((float)(tb + 1) * DIVC);
                float m = (bs + is.x) * dv;
                float var = fmaf(-m, m, (bq + iq.x) * dv);
                m4.x = m; i4.x = rsqrtf(var + EPSV);
            }
            {
                float dv = 1.0f / ((float)(tb + 2) * DIVC);
                float m = (bs + is.y) * dv;
                float var = fmaf(-m, m, (bq + iq.y) * dv);
                m4.y = m; i4.y = rsqrtf(var + EPSV);
            }
            {
                float dv = 1.0f / ((float)(tb + 3) * DIVC);
                float m = (bs + is.z) * dv;
                float var = fmaf(-m, m, (bq + iq.z) * dv);
                m4.z = m; i4.z = rsqrtf(var + EPSV);
            }
            {
                float dv = 1.0f / ((float)(tb + 4) * DIVC);
                float m = (bs + is.w) * dv;
                float var = fmaf(-m, m, (bq + iq.w) * dv);
                m4.w = m; i4.w = rsqrtf(var + EPSV);
            }
            mean4[lane] = m4;
            inv4[lane]  = i4;
        }
    }
    __syncthreads();

    // ======== Pass 2: re-read own 256KB (L2-hot again), normalize, write ========
    {
        const float4 m4 = mean4[lane];
        const float4 i4 = inv4[lane];
        float* ob = out + ((size_t)b * CC) * TT + t0 + 4 * lane;
#pragma unroll
        for (int iblk = 0; iblk < 2; iblk++) {
            float4 v[8];
            float gg[8], bb[8];
#pragma unroll
            for (int u = 0; u < 8; u++) {
                const int c = (iblk * 8 + u) * 32 + w;
                v[u]  = __ldg((const float4*)(xb + (size_t)c * TT));
                gg[u] = __ldg(gains + c);
                bb[u] = __ldg(bias  + c);
            }
#pragma unroll
            for (int u = 0; u < 8; u++) {
                const int c = (iblk * 8 + u) * 32 + w;
                float4 t = v[u];
                float4 o;
                o.x = fmaf((t.x - m4.x) * i4.x, gg[u], bb[u]);
                o.y = fmaf((t.y - m4.y) * i4.y, gg[u], bb[u]);
                o.z = fmaf((t.z - m4.z) * i4.z, gg[u], bb[u]);
                o.w = fmaf((t.w - m4.w) * i4.w, gg[u], bb[u]);
                __stcs((float4*)(ob + (size_t)c * TT), o);
            }
        }
    }
}

extern "C" void kernel_launch(void* const* d_in, const int* in_sizes, int n_in,
                              void* d_out, int out_size) {
    (void)in_sizes; (void)n_in; (void)out_size;
    const float* x     = (const float*)d_in[0];
    const float* gains = (const float*)d_in[1];
    const float* bias  = (const float*)d_in[2];
    float* out = (float*)d_out;

    init_rec_kernel<<<NCTA / 256, 256>>>();
    newNormal_kernel<<<NCTA, NTHREADS>>>(x, gains, bias, out);
}